// round 14
// baseline (speedup 1.0000x reference)
#include <cuda_runtime.h>
#include <cuda_bf16.h>

#define DIM 256
#define NPAIRS 32640          // C(256,2)
#define ROWS 8                // batch rows per block
#define NTHREADS 256

// Dense coefficient matrix: M[i*DIM+j] = (w0+w1)*w0*w1 for pair k=(i,j), i<j; 0 elsewhere.
__device__ float g_M[DIM * DIM];

// perm_mat is lexicographic C(256,2):  k(i,j) = i*(DIM-1) - i*(i-1)/2 + (j-i-1),  i<j.
__global__ void genM_kernel(const float* __restrict__ w) {
    const int i = blockIdx.x;
    const int j = threadIdx.x;
    float v = 0.0f;
    if (i < j) {
        int k = i * (DIM - 1) - (i * (i - 1)) / 2 + (j - i - 1);
        float w0 = __ldg(&w[k]);
        float w1 = __ldg(&w[NPAIRS + k]);
        v = (w0 + w1) * w0 * w1;
    }
    g_M[i * DIM + j] = v;
}

__device__ __forceinline__ unsigned long long splat2(float m) {
    unsigned long long d;
    unsigned int r = __float_as_uint(m);
    asm("mov.b64 %0, {%1, %1};" : "=l"(d) : "r"(r));
    return d;
}

__device__ __forceinline__ void ffma2(unsigned long long& acc,
                                      unsigned long long a,
                                      unsigned long long b) {
    asm("fma.rn.f32x2 %0, %1, %2, %0;" : "+l"(acc) : "l"(a), "l"(b));
}

__device__ __forceinline__ float lo32(unsigned long long p) {
    unsigned int l, h;
    asm("mov.b64 {%0, %1}, %2;" : "=r"(l), "=r"(h) : "l"(p));
    return __uint_as_float(l);
}
__device__ __forceinline__ float hi32(unsigned long long p) {
    unsigned int l, h;
    asm("mov.b64 {%0, %1}, %2;" : "=r"(l), "=r"(h) : "l"(p));
    return __uint_as_float(h);
}

// out[r] = x_r^T M x_r for ROWS rows per block.
// Thread layout: cg = tid&63 owns columns 4cg..4cg+3 (LDG.128 of M row),
//                s  = tid>>6 owns i-stripe {s, s+4, s+8, ...} (64 i's).
// acc[jp][r] packs columns (4cg+2jp, 4cg+2jp+1) for batch row r via fma.rn.f32x2.
// Explicit 4-deep LDG.128 prefetch pipeline -> MLP=4 (R4's 19.9us was MLP=1 latency).
__global__ __launch_bounds__(NTHREADS) void quad_kernel(
    const float* __restrict__ x, float* __restrict__ out, int B)
{
    __shared__ unsigned long long xsD[DIM][ROWS];  // xsD[i][r] = (x[r][i], x[r][i]) splat
    __shared__ float red[NTHREADS / 32][ROWS];

    const int tid  = threadIdx.x;
    const int row0 = blockIdx.x * ROWS;

    // Load ROWS rows of x, transposed + pre-splatted into smem.
    for (int idx = tid; idx < ROWS * DIM; idx += NTHREADS) {
        int r = idx >> 8;
        int c = idx & (DIM - 1);
        float v = (row0 + r < B) ? x[(row0 + r) * DIM + c] : 0.0f;
        xsD[c][r] = splat2(v);
    }
    __syncthreads();

    const int cg = tid & 63;   // column group
    const int s  = tid >> 6;   // i-stripe
    const float4* Mp = reinterpret_cast<const float4*>(g_M) + cg;

    unsigned long long acc[2][ROWS];
#pragma unroll
    for (int jp = 0; jp < 2; jp++)
#pragma unroll
        for (int r = 0; r < ROWS; r++) acc[jp][r] = 0ull;

    // Prologue: 4 LDG.128 in flight.
    float4 buf[4];
#pragma unroll
    for (int p = 0; p < 4; p++)
        buf[p] = __ldg(&Mp[(s + 4 * p) * (DIM / 4)]);

    for (int blk = 0; blk < 16; blk++) {
        float4 cur[4];
#pragma unroll
        for (int p = 0; p < 4; p++) cur[p] = buf[p];

        if (blk < 15) {
#pragma unroll
            for (int p = 0; p < 4; p++)
                buf[p] = __ldg(&Mp[(s + 4 * ((blk + 1) * 4 + p)) * (DIM / 4)]);
        }

#pragma unroll
        for (int p = 0; p < 4; p++) {
            const int i = s + 4 * (blk * 4 + p);
            // 8 rows of splatted x: 4 broadcast LDS.128 (each = 2 u64 rows).
            ulonglong2 xa = *reinterpret_cast<const ulonglong2*>(&xsD[i][0]);
            ulonglong2 xb = *reinterpret_cast<const ulonglong2*>(&xsD[i][2]);
            ulonglong2 xc = *reinterpret_cast<const ulonglong2*>(&xsD[i][4]);
            ulonglong2 xd = *reinterpret_cast<const ulonglong2*>(&xsD[i][6]);
            // M column pairs come packed for free from the float4 load.
            ulonglong2 mp = *reinterpret_cast<const ulonglong2*>(&cur[p]);

            ffma2(acc[0][0], mp.x, xa.x);  ffma2(acc[0][1], mp.x, xa.y);
            ffma2(acc[0][2], mp.x, xb.x);  ffma2(acc[0][3], mp.x, xb.y);
            ffma2(acc[0][4], mp.x, xc.x);  ffma2(acc[0][5], mp.x, xc.y);
            ffma2(acc[0][6], mp.x, xd.x);  ffma2(acc[0][7], mp.x, xd.y);

            ffma2(acc[1][0], mp.y, xa.x);  ffma2(acc[1][1], mp.y, xa.y);
            ffma2(acc[1][2], mp.y, xb.x);  ffma2(acc[1][3], mp.y, xb.y);
            ffma2(acc[1][4], mp.y, xc.x);  ffma2(acc[1][5], mp.y, xc.y);
            ffma2(acc[1][6], mp.y, xd.x);  ffma2(acc[1][7], mp.y, xd.y);
        }
    }

    // Epilogue: contrib[r] = sum over this thread's 4 columns of acc * x[r][j].
    // (x[r][j] distributes over the i-partial sums, so per-thread scaling is legal.)
    float contrib[ROWS];
#pragma unroll
    for (int r = 0; r < ROWS; r++) contrib[r] = 0.0f;

#pragma unroll
    for (int jl = 0; jl < 4; jl++) {
        const int j = 4 * cg + jl;
#pragma unroll
        for (int r = 0; r < ROWS; r++) {
            float a  = (jl & 1) ? hi32(acc[jl >> 1][r]) : lo32(acc[jl >> 1][r]);
            float xv = reinterpret_cast<const float2*>(&xsD[j][r])->x;
            contrib[r] += a * xv;
        }
    }

    // Warp reduction
#pragma unroll
    for (int off = 16; off > 0; off >>= 1) {
#pragma unroll
        for (int r = 0; r < ROWS; r++)
            contrib[r] += __shfl_down_sync(0xffffffffu, contrib[r], off);
    }
    const int lane = tid & 31;
    const int warp = tid >> 5;
    if (lane == 0) {
#pragma unroll
        for (int r = 0; r < ROWS; r++) red[warp][r] = contrib[r];
    }
    __syncthreads();

    if (tid < ROWS) {
        float ssum = 0.0f;
#pragma unroll
        for (int w = 0; w < NTHREADS / 32; w++) ssum += red[w][tid];
        if (row0 + tid < B) out[row0 + tid] = ssum;
    }
}

extern "C" void kernel_launch(void* const* d_in, const int* in_sizes, int n_in,
                              void* d_out, int out_size) {
    const float* x = (const float*)d_in[0];   // [B, 256] float32
    const float* w = (const float*)d_in[1];   // [1, 2, 32640] float32
    // d_in[2] (perm_mat) is lexicographic C(256,2) — recomputed in closed form.
    float* out = (float*)d_out;               // [B, 1] float32

    const int B = in_sizes[0] / DIM;

    genM_kernel<<<DIM, DIM>>>(w);

    const int nblk = (B + ROWS - 1) / ROWS;
    quad_kernel<<<nblk, NTHREADS>>>(x, out, B);
}